// round 13
// baseline (speedup 1.0000x reference)
#include <cuda_runtime.h>
#include <math.h>
#include <stdint.h>

#define BB 64
#define HH 1024
#define INN 1024
#define BH (BB * HH)
#define KSPLIT 8
#define KSLICE (INN / KSPLIT)   // 128
#define NT (KSLICE / 32)        // 4 stages of BK=32

// Scratch (device globals — no allocations allowed).
__device__ float g_part[KSPLIT * 6 * BH];
__device__ float g_lin[6 * BH];
__device__ float g_f[BH];
__device__ float g_o[BH];
__device__ float g_ipv[BH];   // i' * v  (v with bias)
__device__ float g_div[BB];

struct GemmArgs { const float* W[6]; };
struct BiasArgs { const float* b[6]; };

__device__ __forceinline__ uint32_t f2tf(uint32_t fbits) {
    uint32_t r;
    asm("cvt.rna.tf32.f32 %0, %1;" : "=r"(r) : "r"(fbits));
    return r;
}

__device__ __forceinline__ void mma_tf32(float c[4],
                                         uint32_t a0, uint32_t a1, uint32_t a2, uint32_t a3,
                                         uint32_t b0, uint32_t b1) {
    asm("mma.sync.aligned.m16n8k8.row.col.f32.tf32.tf32.f32 "
        "{%0,%1,%2,%3},{%4,%5,%6,%7},{%8,%9},{%0,%1,%2,%3};"
        : "+f"(c[0]), "+f"(c[1]), "+f"(c[2]), "+f"(c[3])
        : "r"(a0), "r"(a1), "r"(a2), "r"(a3), "r"(b0), "r"(b1));
}

__device__ __forceinline__ void cpasync16(uint32_t dst_smem, const void* src) {
    asm volatile("cp.async.cg.shared.global [%0], [%1], 16;"
                 :: "r"(dst_smem), "l"(src));
}

// ---------------------------------------------------------------------------
// Kernel 1: six fused GEMMs on tf32 tensor cores, split-K=8.
// Block tile 64(M) x 128(N) x 128(Kslice); 8 warps as 2(M) x 4(N), warp tile
// 32x32.  ALL data moves global->shared via cp.async (zero register
// residency): 4 stages issued back-to-back in the preamble (one latency
// exposure, per-stage commit groups), compute starts when stage 0 lands.
// fp32 lives in smem; cvt.rna.tf32 runs in the mainloop on idle alu/fma pipes.
// ---------------------------------------------------------------------------
__global__ __launch_bounds__(256, 2) void gemm_kernel(const float* __restrict__ x, GemmArgs args) {
    __shared__ uint32_t xs[NT][64 * 32];    // 32 KB (fp32 bits)
    __shared__ uint32_t ws[NT][128 * 32];   // 64 KB (fp32 bits)

    const int g    = blockIdx.y;
    const int n0   = blockIdx.x * 128;
    const int z    = blockIdx.z;
    const int kf0  = z * (KSLICE / 4);      // base in float4 units (32)
    const float* __restrict__ W = args.W[g];

    const int tid  = threadIdx.x;
    const int lane = tid & 31;
    const int warp = tid >> 5;
    const int wm   = warp & 1;    // M-warp: rows wm*32
    const int wn   = warp >> 1;   // N-warp: cols wn*32

    const float4* __restrict__ x4 = reinterpret_cast<const float4*>(x);
    const float4* __restrict__ W4 = reinterpret_cast<const float4*>(W);

    const int fr  = tid >> 3;     // fill row 0..31
    const int fc  = tid & 7;      // fill float4-col 0..7
    const int fsw = (fc * 4) ^ ((fr & 7) << 2);   // row-xor swizzle (r, r+32 same)

    // ---- preamble: cp.async everything, one commit group per stage ----
#pragma unroll
    for (int t = 0; t < NT; ++t) {
        cpasync16((uint32_t)__cvta_generic_to_shared(&xs[t][fr * 32 + fsw]),
                  &x4[(size_t)fr * 256 + kf0 + t * 8 + fc]);
        cpasync16((uint32_t)__cvta_generic_to_shared(&xs[t][(fr + 32) * 32 + fsw]),
                  &x4[(size_t)(fr + 32) * 256 + kf0 + t * 8 + fc]);
#pragma unroll
        for (int i = 0; i < 4; ++i)
            cpasync16((uint32_t)__cvta_generic_to_shared(&ws[t][(fr + 32 * i) * 32 + fsw]),
                      &W4[(size_t)(n0 + fr + 32 * i) * 256 + kf0 + t * 8 + fc]);
        asm volatile("cp.async.commit_group;" ::: "memory");
    }
    asm volatile("cp.async.wait_group 3;" ::: "memory");   // stage 0 complete
    __syncthreads();

    float acc[2][4][4];
#pragma unroll
    for (int i = 0; i < 2; ++i)
#pragma unroll
        for (int j = 0; j < 4; ++j)
#pragma unroll
            for (int l = 0; l < 4; ++l) acc[i][j][l] = 0.f;

    const int q  = lane >> 2;     // 0..7
    const int tt = lane & 3;      // 0..3
    const int sw = q << 2;

    int acol[4], acolx[4];
#pragma unroll
    for (int kk = 0; kk < 4; ++kk) {
        acol[kk]  = ((kk * 8) + tt) ^ sw;
        acolx[kk] = acol[kk] ^ 4;
    }
    const int arow = (wm * 32 + q) * 32;
    const int brow = (wn * 32 + q) * 32;

    // ---- mainloop: LDS fp32 -> cvt -> MMA; later stages drain in background ----
#pragma unroll
    for (int t = 0; t < NT; ++t) {
        const uint32_t* __restrict__ X  = xs[t];
        const uint32_t* __restrict__ Wt = ws[t];
#pragma unroll
        for (int kk = 0; kk < 4; ++kk) {
            const int c = acol[kk], cx = acolx[kk];
            uint32_t a00 = f2tf(X[arow + c]);
            uint32_t a01 = f2tf(X[arow + 8 * 32 + c]);
            uint32_t a02 = f2tf(X[arow + cx]);
            uint32_t a03 = f2tf(X[arow + 8 * 32 + cx]);
            uint32_t a10 = f2tf(X[arow + 16 * 32 + c]);
            uint32_t a11 = f2tf(X[arow + 24 * 32 + c]);
            uint32_t a12 = f2tf(X[arow + 16 * 32 + cx]);
            uint32_t a13 = f2tf(X[arow + 24 * 32 + cx]);
            uint32_t b00 = f2tf(Wt[brow + c]),           b01 = f2tf(Wt[brow + cx]);
            uint32_t b10 = f2tf(Wt[brow + 8 * 32 + c]),  b11 = f2tf(Wt[brow + 8 * 32 + cx]);
            uint32_t b20 = f2tf(Wt[brow + 16 * 32 + c]), b21 = f2tf(Wt[brow + 16 * 32 + cx]);
            uint32_t b30 = f2tf(Wt[brow + 24 * 32 + c]), b31 = f2tf(Wt[brow + 24 * 32 + cx]);

            mma_tf32(acc[0][0], a00, a01, a02, a03, b00, b01);
            mma_tf32(acc[0][1], a00, a01, a02, a03, b10, b11);
            mma_tf32(acc[0][2], a00, a01, a02, a03, b20, b21);
            mma_tf32(acc[0][3], a00, a01, a02, a03, b30, b31);
            mma_tf32(acc[1][0], a10, a11, a12, a13, b00, b01);
            mma_tf32(acc[1][1], a10, a11, a12, a13, b10, b11);
            mma_tf32(acc[1][2], a10, a11, a12, a13, b20, b21);
            mma_tf32(acc[1][3], a10, a11, a12, a13, b30, b31);
        }

        if (t == 0)      asm volatile("cp.async.wait_group 2;" ::: "memory");
        else if (t == 1) asm volatile("cp.async.wait_group 1;" ::: "memory");
        else if (t == 2) asm volatile("cp.async.wait_group 0;" ::: "memory");
        if (t < NT - 1) __syncthreads();
    }

    // epilogue: write partials
    float* __restrict__ Z = g_part + ((size_t)z * 6 + g) * BH;
#pragma unroll
    for (int fm = 0; fm < 2; ++fm) {
#pragma unroll
        for (int fn = 0; fn < 4; ++fn) {
            const int r0 = wm * 32 + fm * 16 + q;
            const int c0 = n0 + wn * 32 + fn * 8 + 2 * tt;
            *reinterpret_cast<float2*>(&Z[(size_t)r0 * HH + c0]) =
                make_float2(acc[fm][fn][0], acc[fm][fn][1]);
            *reinterpret_cast<float2*>(&Z[(size_t)(r0 + 8) * HH + c0]) =
                make_float2(acc[fm][fn][2], acc[fm][fn][3]);
        }
    }
}

// ---------------------------------------------------------------------------
// Kernel 2: fold split-K partials + bias + gates + n_t + m_t + divisor.
// ---------------------------------------------------------------------------
__global__ __launch_bounds__(256) void gates_kernel(BiasArgs ba,
                                                    const float* __restrict__ n_in,
                                                    const float* __restrict__ m_in,
                                                    float* __restrict__ out) {
    __shared__ float sbuf[8];
    const int b   = blockIdx.x;
    const int tid = threadIdx.x;

    float* __restrict__ outN = out + (size_t)BH + (size_t)BB * HH * HH;
    float* __restrict__ outM = outN + BH;

    float local = 0.f;
#pragma unroll
    for (int j = 0; j < 4; ++j) {
        int h   = tid + j * 256;
        int idx = b * HH + h;

        float zz[6];
#pragma unroll
        for (int g = 0; g < 6; ++g) {
            float s = ba.b[g][h];
#pragma unroll
            for (int z = 0; z < KSPLIT; ++z)
                s += g_part[((size_t)z * 6 + g) * BH + idx];
            zz[g] = s;
        }
        float it = zz[0];
        float ft = zz[1];
        float ot = zz[2];
        float qv = zz[3];
        float kv = zz[4] * 0.03125f;   // 1/sqrt(1024)
        float vv = zz[5];

        float f_sig = 1.f / (1.f + expf(-ft));
        float o_sig = 1.f / (1.f + expf(-ot));
        float ls = (ft >= 0.f) ? -log1pf(expf(-ft)) : (ft - log1pf(expf(ft)));
        float mt = fmaxf(ls + m_in[idx], it);
        float ip = expf(it - mt);
        float nt = f_sig * n_in[idx] + ip * kv;

        g_f[idx]   = f_sig;
        g_o[idx]   = o_sig;
        g_ipv[idx] = ip * vv;
        g_lin[3 * BH + idx] = qv;
        g_lin[4 * BH + idx] = kv;

        outN[idx] = nt;
        outM[idx] = mt;
        local += nt * qv;
    }

#pragma unroll
    for (int off = 16; off > 0; off >>= 1)
        local += __shfl_down_sync(0xffffffffu, local, off);
    int lane = tid & 31, w = tid >> 5;
    if (lane == 0) sbuf[w] = local;
    __syncthreads();
    if (w == 0) {
        float v = (lane < 8) ? sbuf[lane] : 0.f;
#pragma unroll
        for (int off = 4; off > 0; off >>= 1)
            v += __shfl_down_sync(0xffffffffu, v, off);
        if (lane == 0) g_div[b] = fmaxf(fabsf(v), 1.f);
    }
}

// ---------------------------------------------------------------------------
// Kernel 3: fused C update + h.  One warp per row, 32 rows per block (1024 thr).
//   C_t[b,r,j] = f[b,r]*C[b,r,j] + ipv[b,r] * k[b,j]
//   h[b,r]     = o[b,r] * dot(C_t[b,r,:], q[b,:]) / div[b]
// ---------------------------------------------------------------------------
__global__ __launch_bounds__(1024) void update_kernel(const float* __restrict__ C,
                                                      float* __restrict__ out) {
    __shared__ float4 ks[256], qs[256];
    const int tid  = threadIdx.x;
    const int lane = tid & 31;
    const int b    = blockIdx.x >> 5;                 // 32 blocks per batch
    const int row  = blockIdx.x * 32 + (tid >> 5);    // this warp's row

    if (tid < 256) {
        ks[tid] = reinterpret_cast<const float4*>(g_lin + 4 * BH + b * HH)[tid];
    } else if (tid < 512) {
        qs[tid - 256] = reinterpret_cast<const float4*>(g_lin + 3 * BH + b * HH)[tid - 256];
    }
    __syncthreads();

    const float f   = g_f[row];
    const float ipv = g_ipv[row];

    const float4* __restrict__ Cr = reinterpret_cast<const float4*>(C + (size_t)row * HH);
    float4* __restrict__ Or = reinterpret_cast<float4*>(out + (size_t)BH + (size_t)row * HH);

    float4 c4[8];
#pragma unroll
    for (int j = 0; j < 8; ++j)
        c4[j] = __ldcs(Cr + j * 32 + lane);

    float dot = 0.f;
#pragma unroll
    for (int j = 0; j < 8; ++j) {
        float4 k4 = ks[j * 32 + lane];
        float4 q4 = qs[j * 32 + lane];
        float4 o;
        o.x = fmaf(f, c4[j].x, ipv * k4.x);
        o.y = fmaf(f, c4[j].y, ipv * k4.y);
        o.z = fmaf(f, c4[j].z, ipv * k4.z);
        o.w = fmaf(f, c4[j].w, ipv * k4.w);
        __stcs(Or + j * 32 + lane, o);
        dot = fmaf(o.x, q4.x, dot);
        dot = fmaf(o.y, q4.y, dot);
        dot = fmaf(o.z, q4.z, dot);
        dot = fmaf(o.w, q4.w, dot);
    }

#pragma unroll
    for (int off = 16; off > 0; off >>= 1)
        dot += __shfl_down_sync(0xffffffffu, dot, off);
    if (lane == 0)
        out[row] = g_o[row] * dot / g_div[b];
}

// ---------------------------------------------------------------------------
// Launch
// ---------------------------------------------------------------------------
extern "C" void kernel_launch(void* const* d_in, const int* in_sizes, int n_in,
                              void* d_out, int out_size) {
    const float* x = (const float*)d_in[0];
    const float* C = (const float*)d_in[1];
    const float* n = (const float*)d_in[2];
    const float* m = (const float*)d_in[3];

    GemmArgs ga;
    BiasArgs ba;
    for (int g = 0; g < 6; ++g) {
        ga.W[g] = (const float*)d_in[4 + 2 * g];
        ba.b[g] = (const float*)d_in[5 + 2 * g];
    }

    float* out = (float*)d_out;

    gemm_kernel<<<dim3(8, 6, KSPLIT), 256>>>(x, ga);
    gates_kernel<<<BB, 256>>>(ba, n, m, out);
    update_kernel<<<BB * HH / 32, 1024>>>(C, out);
}

// round 14
// speedup vs baseline: 1.3516x; 1.3516x over previous
#include <cuda_runtime.h>
#include <math.h>
#include <stdint.h>

#define BB 64
#define HH 1024
#define INN 1024
#define BH (BB * HH)
#define KSPLIT 8
#define KSLICE (INN / KSPLIT)   // 128
#define NT (KSLICE / 32)        // 4 stages of BK=32

// Scratch (device globals — no allocations allowed).
__device__ float g_part[KSPLIT * 6 * BH];
__device__ float g_lin[6 * BH];
__device__ float g_f[BH];
__device__ float g_o[BH];
__device__ float g_ipv[BH];   // i' * v  (v with bias)
__device__ float g_div[BB];

struct GemmArgs { const float* W[6]; };
struct BiasArgs { const float* b[6]; };

__device__ __forceinline__ uint32_t f2tf(float f) {
    uint32_t r;
    asm("cvt.rna.tf32.f32 %0, %1;" : "=r"(r) : "f"(f));
    return r;
}

__device__ __forceinline__ void mma_tf32(float c[4],
                                         uint32_t a0, uint32_t a1, uint32_t a2, uint32_t a3,
                                         uint32_t b0, uint32_t b1) {
    asm("mma.sync.aligned.m16n8k8.row.col.f32.tf32.tf32.f32 "
        "{%0,%1,%2,%3},{%4,%5,%6,%7},{%8,%9},{%0,%1,%2,%3};"
        : "+f"(c[0]), "+f"(c[1]), "+f"(c[2]), "+f"(c[3])
        : "r"(a0), "r"(a1), "r"(a2), "r"(a3), "r"(b0), "r"(b1));
}

// ---------------------------------------------------------------------------
// Kernel 1: six fused GEMMs on tf32 tensor cores, split-K=8.
// Block tile 64(M) x 64(N) x 128(Kslice); 8 warps as 2(M) x 4(N), warp tile
// 32x16.  smem = 64KB -> 3 resident blocks/SM so fill latency of one block
// hides under compute of the other two.  x staged first (L2-resident: the
// 32KB z-slice is shared by all 96 blocks of that z), then W; mainloop is
// pure LDS+MMA with no syncs.
// ---------------------------------------------------------------------------
__global__ __launch_bounds__(256, 3) void gemm_kernel(const float* __restrict__ x, GemmArgs args) {
    __shared__ uint32_t xs[NT][64 * 32];    // 32 KB
    __shared__ uint32_t ws[NT][64 * 32];    // 32 KB

    const int g    = blockIdx.y;
    const int n0   = blockIdx.x * 64;
    const int z    = blockIdx.z;
    const int kf0  = z * (KSLICE / 4);      // base in float4 units (32)
    const float* __restrict__ W = args.W[g];

    const int tid  = threadIdx.x;
    const int lane = tid & 31;
    const int warp = tid >> 5;
    const int wm   = warp & 1;    // M-warp: rows wm*32
    const int wn   = warp >> 1;   // N-warp: cols wn*16 (0..3)

    const float4* __restrict__ x4 = reinterpret_cast<const float4*>(x);
    const float4* __restrict__ W4 = reinterpret_cast<const float4*>(W);

    const int fr  = tid >> 3;     // fill row 0..31
    const int fc  = tid & 7;      // fill float4-col 0..7
    const int fsw = (fc * 4) ^ ((fr & 7) << 2);   // row-xor swizzle (r, r+32 same)

    auto cvt4 = [](float4 v) {
        return make_uint4(f2tf(v.x), f2tf(v.y), f2tf(v.z), f2tf(v.w));
    };

    // ---- stage x (mostly L2 hits), then W (DRAM), each max-MLP batched ----
    {
        float4 xr[2 * NT];
#pragma unroll
        for (int t = 0; t < NT; ++t) {
            xr[2 * t]     = x4[(size_t)fr * 256 + kf0 + t * 8 + fc];
            xr[2 * t + 1] = x4[(size_t)(fr + 32) * 256 + kf0 + t * 8 + fc];
        }
#pragma unroll
        for (int t = 0; t < NT; ++t) {
            *reinterpret_cast<uint4*>(&xs[t][fr * 32 + fsw])        = cvt4(xr[2 * t]);
            *reinterpret_cast<uint4*>(&xs[t][(fr + 32) * 32 + fsw]) = cvt4(xr[2 * t + 1]);
        }
    }
    {
        float4 wr[2 * NT];
#pragma unroll
        for (int t = 0; t < NT; ++t) {
            wr[2 * t]     = W4[(size_t)(n0 + fr) * 256 + kf0 + t * 8 + fc];
            wr[2 * t + 1] = W4[(size_t)(n0 + fr + 32) * 256 + kf0 + t * 8 + fc];
        }
#pragma unroll
        for (int t = 0; t < NT; ++t) {
            *reinterpret_cast<uint4*>(&ws[t][fr * 32 + fsw])        = cvt4(wr[2 * t]);
            *reinterpret_cast<uint4*>(&ws[t][(fr + 32) * 32 + fsw]) = cvt4(wr[2 * t + 1]);
        }
    }
    __syncthreads();

    float acc[2][2][4];
#pragma unroll
    for (int i = 0; i < 2; ++i)
#pragma unroll
        for (int j = 0; j < 2; ++j)
#pragma unroll
            for (int l = 0; l < 4; ++l) acc[i][j][l] = 0.f;

    const int q  = lane >> 2;     // 0..7
    const int tt = lane & 3;      // 0..3
    const int sw = q << 2;

    int acol[4], acolx[4];
#pragma unroll
    for (int kk = 0; kk < 4; ++kk) {
        acol[kk]  = ((kk * 8) + tt) ^ sw;
        acolx[kk] = acol[kk] ^ 4;
    }
    const int arow = (wm * 32 + q) * 32;
    const int brow = (wn * 16 + q) * 32;

    // ---- pure-MMA mainloop: no global loads, no syncs ----
#pragma unroll
    for (int t = 0; t < NT; ++t) {
        const uint32_t* __restrict__ X  = xs[t];
        const uint32_t* __restrict__ Wt = ws[t];
#pragma unroll
        for (int kk = 0; kk < 4; ++kk) {
            const int c = acol[kk], cx = acolx[kk];
            uint32_t a00 = X[arow + c];
            uint32_t a01 = X[arow + 8 * 32 + c];
            uint32_t a02 = X[arow + cx];
            uint32_t a03 = X[arow + 8 * 32 + cx];
            uint32_t a10 = X[arow + 16 * 32 + c];
            uint32_t a11 = X[arow + 24 * 32 + c];
            uint32_t a12 = X[arow + 16 * 32 + cx];
            uint32_t a13 = X[arow + 24 * 32 + cx];
            uint32_t b00 = Wt[brow + c],          b01 = Wt[brow + cx];
            uint32_t b10 = Wt[brow + 8 * 32 + c], b11 = Wt[brow + 8 * 32 + cx];

            mma_tf32(acc[0][0], a00, a01, a02, a03, b00, b01);
            mma_tf32(acc[0][1], a00, a01, a02, a03, b10, b11);
            mma_tf32(acc[1][0], a10, a11, a12, a13, b00, b01);
            mma_tf32(acc[1][1], a10, a11, a12, a13, b10, b11);
        }
    }

    // epilogue: write partials
    float* __restrict__ Z = g_part + ((size_t)z * 6 + g) * BH;
#pragma unroll
    for (int fm = 0; fm < 2; ++fm) {
#pragma unroll
        for (int fn = 0; fn < 2; ++fn) {
            const int r0 = wm * 32 + fm * 16 + q;
            const int c0 = n0 + wn * 16 + fn * 8 + 2 * tt;
            *reinterpret_cast<float2*>(&Z[(size_t)r0 * HH + c0]) =
                make_float2(acc[fm][fn][0], acc[fm][fn][1]);
            *reinterpret_cast<float2*>(&Z[(size_t)(r0 + 8) * HH + c0]) =
                make_float2(acc[fm][fn][2], acc[fm][fn][3]);
        }
    }
}

// ---------------------------------------------------------------------------
// Kernel 2: fold split-K partials + bias + gates + n_t + m_t + divisor.
// Vectorized: each thread owns 4 consecutive h (one float4 column set).
// ---------------------------------------------------------------------------
__global__ __launch_bounds__(256) void gates_kernel(BiasArgs ba,
                                                    const float* __restrict__ n_in,
                                                    const float* __restrict__ m_in,
                                                    float* __restrict__ out) {
    __shared__ float sbuf[8];
    const int b   = blockIdx.x;
    const int tid = threadIdx.x;       // float4 index within the row (0..255)

    float* __restrict__ outN = out + (size_t)BH + (size_t)BB * HH * HH;
    float* __restrict__ outM = outN + BH;

    // fold partials (vector loads, same accumulation order as before)
    float4 zz[6];
#pragma unroll
    for (int g = 0; g < 6; ++g) {
        float4 s = reinterpret_cast<const float4*>(ba.b[g])[tid];
#pragma unroll
        for (int z = 0; z < KSPLIT; ++z) {
            float4 p = reinterpret_cast<const float4*>(
                g_part + ((size_t)z * 6 + g) * BH + (size_t)b * HH)[tid];
            s.x += p.x; s.y += p.y; s.z += p.z; s.w += p.w;
        }
        zz[g] = s;
    }

    float4 nin4 = reinterpret_cast<const float4*>(n_in + (size_t)b * HH)[tid];
    float4 min4 = reinterpret_cast<const float4*>(m_in + (size_t)b * HH)[tid];

    const float* it4 = &zz[0].x;
    const float* ft4 = &zz[1].x;
    const float* ot4 = &zz[2].x;
    const float* qv4 = &zz[3].x;
    const float* kr4 = &zz[4].x;
    const float* vv4 = &zz[5].x;
    const float* nI  = &nin4.x;
    const float* mI  = &min4.x;

    float4 fO, oO, ipvO, qO, kO, ntO, mtO;
    float* fO_  = &fO.x;
    float* oO_  = &oO.x;
    float* ipO_ = &ipvO.x;
    float* qO_  = &qO.x;
    float* kO_  = &kO.x;
    float* ntO_ = &ntO.x;
    float* mtO_ = &mtO.x;

    float local = 0.f;
#pragma unroll
    for (int c = 0; c < 4; ++c) {
        float it = it4[c];
        float ft = ft4[c];
        float ot = ot4[c];
        float qv = qv4[c];
        float kv = kr4[c] * 0.03125f;   // 1/sqrt(1024)
        float vv = vv4[c];

        float f_sig = 1.f / (1.f + expf(-ft));
        float o_sig = 1.f / (1.f + expf(-ot));
        float ls = (ft >= 0.f) ? -log1pf(expf(-ft)) : (ft - log1pf(expf(ft)));
        float mt = fmaxf(ls + mI[c], it);
        float ip = expf(it - mt);
        float nt = f_sig * nI[c] + ip * kv;

        fO_[c]  = f_sig;
        oO_[c]  = o_sig;
        ipO_[c] = ip * vv;
        qO_[c]  = qv;
        kO_[c]  = kv;
        ntO_[c] = nt;
        mtO_[c] = mt;
        local += nt * qv;
    }

    reinterpret_cast<float4*>(g_f   + (size_t)b * HH)[tid] = fO;
    reinterpret_cast<float4*>(g_o   + (size_t)b * HH)[tid] = oO;
    reinterpret_cast<float4*>(g_ipv + (size_t)b * HH)[tid] = ipvO;
    reinterpret_cast<float4*>(g_lin + 3 * BH + (size_t)b * HH)[tid] = qO;
    reinterpret_cast<float4*>(g_lin + 4 * BH + (size_t)b * HH)[tid] = kO;
    reinterpret_cast<float4*>(outN + (size_t)b * HH)[tid] = ntO;
    reinterpret_cast<float4*>(outM + (size_t)b * HH)[tid] = mtO;

#pragma unroll
    for (int off = 16; off > 0; off >>= 1)
        local += __shfl_down_sync(0xffffffffu, local, off);
    int lane = tid & 31, w = tid >> 5;
    if (lane == 0) sbuf[w] = local;
    __syncthreads();
    if (w == 0) {
        float v = (lane < 8) ? sbuf[lane] : 0.f;
#pragma unroll
        for (int off = 4; off > 0; off >>= 1)
            v += __shfl_down_sync(0xffffffffu, v, off);
        if (lane == 0) g_div[b] = fmaxf(fabsf(v), 1.f);
    }
}

// ---------------------------------------------------------------------------
// Kernel 3: fused C update + h.  One warp per row, 32 rows per block (1024 thr).
//   C_t[b,r,j] = f[b,r]*C[b,r,j] + ipv[b,r] * k[b,j]
//   h[b,r]     = o[b,r] * dot(C_t[b,r,:], q[b,:]) / div[b]
// ---------------------------------------------------------------------------
__global__ __launch_bounds__(1024) void update_kernel(const float* __restrict__ C,
                                                      float* __restrict__ out) {
    __shared__ float4 ks[256], qs[256];
    const int tid  = threadIdx.x;
    const int lane = tid & 31;
    const int b    = blockIdx.x >> 5;                 // 32 blocks per batch
    const int row  = blockIdx.x * 32 + (tid >> 5);    // this warp's row

    if (tid < 256) {
        ks[tid] = reinterpret_cast<const float4*>(g_lin + 4 * BH + b * HH)[tid];
    } else if (tid < 512) {
        qs[tid - 256] = reinterpret_cast<const float4*>(g_lin + 3 * BH + b * HH)[tid - 256];
    }
    __syncthreads();

    const float f   = g_f[row];
    const float ipv = g_ipv[row];

    const float4* __restrict__ Cr = reinterpret_cast<const float4*>(C + (size_t)row * HH);
    float4* __restrict__ Or = reinterpret_cast<float4*>(out + (size_t)BH + (size_t)row * HH);

    float4 c4[8];
#pragma unroll
    for (int j = 0; j < 8; ++j)
        c4[j] = __ldcs(Cr + j * 32 + lane);

    float dot = 0.f;
#pragma unroll
    for (int j = 0; j < 8; ++j) {
        float4 k4 = ks[j * 32 + lane];
        float4 q4 = qs[j * 32 + lane];
        float4 o;
        o.x = fmaf(f, c4[j].x, ipv * k4.x);
        o.y = fmaf(f, c4[j].y, ipv * k4.y);
        o.z = fmaf(f, c4[j].z, ipv * k4.z);
        o.w = fmaf(f, c4[j].w, ipv * k4.w);
        __stcs(Or + j * 32 + lane, o);
        dot = fmaf(o.x, q4.x, dot);
        dot = fmaf(o.y, q4.y, dot);
        dot = fmaf(o.z, q4.z, dot);
        dot = fmaf(o.w, q4.w, dot);
    }

#pragma unroll
    for (int off = 16; off > 0; off >>= 1)
        dot += __shfl_down_sync(0xffffffffu, dot, off);
    if (lane == 0)
        out[row] = g_o[row] * dot / g_div[b];
}

// ---------------------------------------------------------------------------
// Launch
// ---------------------------------------------------------------------------
extern "C" void kernel_launch(void* const* d_in, const int* in_sizes, int n_in,
                              void* d_out, int out_size) {
    const float* x = (const float*)d_in[0];
    const float* C = (const float*)d_in[1];
    const float* n = (const float*)d_in[2];
    const float* m = (const float*)d_in[3];

    GemmArgs ga;
    BiasArgs ba;
    for (int g = 0; g < 6; ++g) {
        ga.W[g] = (const float*)d_in[4 + 2 * g];
        ba.b[g] = (const float*)d_in[5 + 2 * g];
    }

    float* out = (float*)d_out;

    gemm_kernel<<<dim3(16, 6, KSPLIT), 256>>>(x, ga);
    gates_kernel<<<BB, 256>>>(ba, n, m, out);
    update_kernel<<<BB * HH / 32, 1024>>>(C, out);
}

// round 16
// speedup vs baseline: 1.3579x; 1.0047x over previous
#include <cuda_runtime.h>
#include <cuda_fp16.h>
#include <math.h>
#include <stdint.h>

#define BB 64
#define HH 1024
#define INN 1024
#define BH (BB * HH)
#define KSPLIT 8
#define KSLICE (INN / KSPLIT)   // 128 floats per K slice
#define NT 2                    // 2 stages of BK=64 halves

// Scratch (device globals — no allocations allowed).
__device__ float g_part[KSPLIT * 6 * BH];
__device__ float g_lin[6 * BH];
__device__ float g_f[BH];
__device__ float g_o[BH];
__device__ float g_ipv[BH];   // i' * v  (v with bias)
__device__ float g_div[BB];

struct GemmArgs { const float* W[6]; };
struct BiasArgs { const float* b[6]; };

__device__ __forceinline__ uint32_t packh2(float lo, float hi) {
    __half2 h = __floats2half2_rn(lo, hi);   // .x = lo (low half), .y = hi
    return *reinterpret_cast<uint32_t*>(&h);
}

__device__ __forceinline__ void mma_f16(float c[4],
                                        uint32_t a0, uint32_t a1, uint32_t a2, uint32_t a3,
                                        uint32_t b0, uint32_t b1) {
    asm("mma.sync.aligned.m16n8k16.row.col.f32.f16.f16.f32 "
        "{%0,%1,%2,%3},{%4,%5,%6,%7},{%8,%9},{%0,%1,%2,%3};"
        : "+f"(c[0]), "+f"(c[1]), "+f"(c[2]), "+f"(c[3])
        : "r"(a0), "r"(a1), "r"(a2), "r"(a3), "r"(b0), "r"(b1));
}

// ---------------------------------------------------------------------------
// Kernel 1: six fused GEMMs on fp16 tensor cores (m16n8k16), split-K=8.
// Block tile 64(M) x 64(N) x 128(Kslice); 8 warps as 2(M) x 4(N), warp tile
// 32x16.  fp16 halves LDS traffic, MMA count, and smem (32KB -> 4 resident
// blocks/SM).  smem rows are BK=64 halves = 32 uint32 = 128B with the proven
// XOR swizzle; fragment loads are conflict-free.
// ---------------------------------------------------------------------------
__global__ __launch_bounds__(256, 4) void gemm_kernel(const float* __restrict__ x, GemmArgs args) {
    __shared__ uint32_t xs[NT][64 * 32];    // 16 KB (half2 pairs)
    __shared__ uint32_t ws[NT][64 * 32];    // 16 KB

    const int g    = blockIdx.y;
    const int n0   = blockIdx.x * 64;
    const int z    = blockIdx.z;
    const int kb   = z * 32;                // slice base in float4 units
    const float* __restrict__ W = args.W[g];

    const int tid  = threadIdx.x;
    const int lane = tid & 31;
    const int warp = tid >> 5;
    const int wm   = warp & 1;    // M-warp: rows wm*32
    const int wn   = warp >> 1;   // N-warp: cols wn*16

    const float4* __restrict__ x4 = reinterpret_cast<const float4*>(x);
    const float4* __restrict__ W4 = reinterpret_cast<const float4*>(W);

    // Fill: each thread owns 2 uint4 slots per (tile,stage).
    // u4 slot -> row (0..63), c4 (0..7); source = 2 consecutive float4.
    auto fill_tile = [&](uint32_t* dst, const float4* src4, int rowbase, int st) {
#pragma unroll
        for (int i = 0; i < 2; ++i) {
            int u4  = tid * 2 + i;
            int r   = u4 >> 3;
            int c4  = u4 & 7;
            float4 f0 = src4[(size_t)(rowbase + r) * 256 + kb + st * 16 + c4 * 2];
            float4 f1 = src4[(size_t)(rowbase + r) * 256 + kb + st * 16 + c4 * 2 + 1];
            uint4 v = make_uint4(packh2(f0.x, f0.y), packh2(f0.z, f0.w),
                                 packh2(f1.x, f1.y), packh2(f1.z, f1.w));
            int idx = r * 32 + ((c4 * 4) ^ ((r & 7) << 2));
            *reinterpret_cast<uint4*>(&dst[idx]) = v;
        }
    };

#pragma unroll
    for (int st = 0; st < NT; ++st) {
        fill_tile(xs[st], x4, 0, st);
        fill_tile(ws[st], W4, n0, st);
    }
    __syncthreads();

    float acc[2][2][4];
#pragma unroll
    for (int i = 0; i < 2; ++i)
#pragma unroll
        for (int j = 0; j < 2; ++j)
#pragma unroll
            for (int l = 0; l < 4; ++l) acc[i][j][l] = 0.f;

    const int q  = lane >> 2;     // 0..7
    const int tt = lane & 3;      // 0..3
    const int sw = q << 2;

    const int arow = (wm * 32 + q) * 32;      // + fm*16*32
    const int brow = (wn * 16 + q) * 32;      // + fn*8*32

    // ---- mainloop: pure LDS + MMA, no syncs ----
#pragma unroll
    for (int t = 0; t < NT; ++t) {
        const uint32_t* __restrict__ X  = xs[t];
        const uint32_t* __restrict__ Wt = ws[t];
#pragma unroll
        for (int kk = 0; kk < 4; ++kk) {
            const int ca  = (kk * 8 + tt) ^ sw;
            const int ca4 = ca ^ 4;

            // A fragments (rows wm*32 + {0,8} and {16,24})
            uint32_t a00 = X[arow + ca];
            uint32_t a01 = X[arow + 8 * 32 + ca];
            uint32_t a02 = X[arow + ca4];
            uint32_t a03 = X[arow + 8 * 32 + ca4];
            uint32_t a10 = X[arow + 16 * 32 + ca];
            uint32_t a11 = X[arow + 24 * 32 + ca];
            uint32_t a12 = X[arow + 16 * 32 + ca4];
            uint32_t a13 = X[arow + 24 * 32 + ca4];

            // B fragments (cols wn*16 + {0,8})
            uint32_t b00 = Wt[brow + ca],          b01 = Wt[brow + ca4];
            uint32_t b10 = Wt[brow + 8 * 32 + ca], b11 = Wt[brow + 8 * 32 + ca4];

            mma_f16(acc[0][0], a00, a01, a02, a03, b00, b01);
            mma_f16(acc[0][1], a00, a01, a02, a03, b10, b11);
            mma_f16(acc[1][0], a10, a11, a12, a13, b00, b01);
            mma_f16(acc[1][1], a10, a11, a12, a13, b10, b11);
        }
    }

    // epilogue: write partials
    float* __restrict__ Z = g_part + ((size_t)z * 6 + g) * BH;
#pragma unroll
    for (int fm = 0; fm < 2; ++fm) {
#pragma unroll
        for (int fn = 0; fn < 2; ++fn) {
            const int r0 = wm * 32 + fm * 16 + q;
            const int c0 = n0 + wn * 16 + fn * 8 + 2 * tt;
            *reinterpret_cast<float2*>(&Z[(size_t)r0 * HH + c0]) =
                make_float2(acc[fm][fn][0], acc[fm][fn][1]);
            *reinterpret_cast<float2*>(&Z[(size_t)(r0 + 8) * HH + c0]) =
                make_float2(acc[fm][fn][2], acc[fm][fn][3]);
        }
    }
}

// ---------------------------------------------------------------------------
// Kernel 2: fold split-K partials + bias + gates + n_t + m_t + divisor.
// Vectorized: each thread owns 4 consecutive h.
// ---------------------------------------------------------------------------
__global__ __launch_bounds__(256) void gates_kernel(BiasArgs ba,
                                                    const float* __restrict__ n_in,
                                                    const float* __restrict__ m_in,
                                                    float* __restrict__ out) {
    __shared__ float sbuf[8];
    const int b   = blockIdx.x;
    const int tid = threadIdx.x;       // float4 index within the row (0..255)

    float* __restrict__ outN = out + (size_t)BH + (size_t)BB * HH * HH;
    float* __restrict__ outM = outN + BH;

    float4 zz[6];
#pragma unroll
    for (int g = 0; g < 6; ++g) {
        float4 s = reinterpret_cast<const float4*>(ba.b[g])[tid];
#pragma unroll
        for (int z = 0; z < KSPLIT; ++z) {
            float4 p = reinterpret_cast<const float4*>(
                g_part + ((size_t)z * 6 + g) * BH + (size_t)b * HH)[tid];
            s.x += p.x; s.y += p.y; s.z += p.z; s.w += p.w;
        }
        zz[g] = s;
    }

    float4 nin4 = reinterpret_cast<const float4*>(n_in + (size_t)b * HH)[tid];
    float4 min4 = reinterpret_cast<const float4*>(m_in + (size_t)b * HH)[tid];

    const float* it4 = &zz[0].x; const float* ft4 = &zz[1].x;
    const float* ot4 = &zz[2].x; const float* qv4 = &zz[3].x;
    const float* kr4 = &zz[4].x; const float* vv4 = &zz[5].x;
    const float* nI = &nin4.x;   const float* mI = &min4.x;

    float4 fO, oO, ipvO, qO, kO, ntO, mtO;
    float *fO_ = &fO.x, *oO_ = &oO.x, *ipO_ = &ipvO.x, *qO_ = &qO.x,
          *kO_ = &kO.x, *ntO_ = &ntO.x, *mtO_ = &mtO.x;

    float local = 0.f;
#pragma unroll
    for (int c = 0; c < 4; ++c) {
        float it = it4[c], ft = ft4[c], ot = ot4[c], qv = qv4[c];
        float kv = kr4[c] * 0.03125f;   // 1/sqrt(1024)
        float vv = vv4[c];

        float f_sig = 1.f / (1.f + expf(-ft));
        float o_sig = 1.f / (1.f + expf(-ot));
        float ls = (ft >= 0.f) ? -log1pf(expf(-ft)) : (ft - log1pf(expf(ft)));
        float mt = fmaxf(ls + mI[c], it);
        float ip = expf(it - mt);
        float nt = f_sig * nI[c] + ip * kv;

        fO_[c] = f_sig; oO_[c] = o_sig; ipO_[c] = ip * vv;
        qO_[c] = qv;    kO_[c] = kv;    ntO_[c] = nt;   mtO_[c] = mt;
        local += nt * qv;
    }

    reinterpret_cast<float4*>(g_f   + (size_t)b * HH)[tid] = fO;
    reinterpret_cast<float4*>(g_o   + (size_t)b * HH)[tid] = oO;
    reinterpret_cast<float4*>(g_ipv + (size_t)b * HH)[tid] = ipvO;
    reinterpret_cast<float4*>(g_lin + 3 * BH + (size_t)b * HH)[tid] = qO;
    reinterpret_cast<float4*>(g_lin + 4 * BH + (size_t)b * HH)[tid] = kO;
    reinterpret_cast<float4*>(outN + (size_t)b * HH)[tid] = ntO;
    reinterpret_cast<float4*>(outM + (size_t)b * HH)[tid] = mtO;

#pragma unroll
    for (int off = 16; off > 0; off >>= 1)
        local += __shfl_down_sync(0xffffffffu, local, off);
    int lane = tid & 31, w = tid >> 5;
    if (lane == 0) sbuf[w] = local;
    __syncthreads();
    if (w == 0) {
        float v = (lane < 8) ? sbuf[lane] : 0.f;
#pragma unroll
        for (int off = 4; off > 0; off >>= 1)
            v += __shfl_down_sync(0xffffffffu, v, off);
        if (lane == 0) g_div[b] = fmaxf(fabsf(v), 1.f);
    }
}

// ---------------------------------------------------------------------------
// Kernel 3: fused C update + h.  One warp per row, 32 rows per block (1024 thr).
//   C_t[b,r,j] = f[b,r]*C[b,r,j] + ipv[b,r] * k[b,j]
//   h[b,r]     = o[b,r] * dot(C_t[b,r,:], q[b,:]) / div[b]
// ---------------------------------------------------------------------------
__global__ __launch_bounds__(1024) void update_kernel(const float* __restrict__ C,
                                                      float* __restrict__ out) {
    __shared__ float4 ks[256], qs[256];
    const int tid  = threadIdx.x;
    const int lane = tid & 31;
    const int b    = blockIdx.x >> 5;                 // 32 blocks per batch
    const int row  = blockIdx.x * 32 + (tid >> 5);    // this warp's row

    if (tid < 256) {
        ks[tid] = reinterpret_cast<const float4*>(g_lin + 4 * BH + b * HH)[tid];
    } else if (tid < 512) {
        qs[tid - 256] = reinterpret_cast<const float4*>(g_lin + 3 * BH + b * HH)[tid - 256];
    }
    __syncthreads();

    const float f   = g_f[row];
    const float ipv = g_ipv[row];

    const float4* __restrict__ Cr = reinterpret_cast<const float4*>(C + (size_t)row * HH);
    float4* __restrict__ Or = reinterpret_cast<float4*>(out + (size_t)BH + (size_t)row * HH);

    float4 c4[8];
#pragma unroll
    for (int j = 0; j < 8; ++j)
        c4[j] = __ldcs(Cr + j * 32 + lane);

    float dot = 0.f;
#pragma unroll
    for (int j = 0; j < 8; ++j) {
        float4 k4 = ks[j * 32 + lane];
        float4 q4 = qs[j * 32 + lane];
        float4 o;
        o.x = fmaf(f, c4[j].x, ipv * k4.x);
        o.y = fmaf(f, c4[j].y, ipv * k4.y);
        o.z = fmaf(f, c4[j].z, ipv * k4.z);
        o.w = fmaf(f, c4[j].w, ipv * k4.w);
        __stcs(Or + j * 32 + lane, o);
        dot = fmaf(o.x, q4.x, dot);
        dot = fmaf(o.y, q4.y, dot);
        dot = fmaf(o.z, q4.z, dot);
        dot = fmaf(o.w, q4.w, dot);
    }

#pragma unroll
    for (int off = 16; off > 0; off >>= 1)
        dot += __shfl_down_sync(0xffffffffu, dot, off);
    if (lane == 0)
        out[row] = g_o[row] * dot / g_div[b];
}

// ---------------------------------------------------------------------------
// Launch
// ---------------------------------------------------------------------------
extern "C" void kernel_launch(void* const* d_in, const int* in_sizes, int n_in,
                              void* d_out, int out_size) {
    const float* x = (const float*)d_in[0];
    const float* C = (const float*)d_in[1];
    const float* n = (const float*)d_in[2];
    const float* m = (const float*)d_in[3];

    GemmArgs ga;
    BiasArgs ba;
    for (int g = 0; g < 6; ++g) {
        ga.W[g] = (const float*)d_in[4 + 2 * g];
        ba.b[g] = (const float*)d_in[5 + 2 * g];
    }

    float* out = (float*)d_out;

    gemm_kernel<<<dim3(16, 6, KSPLIT), 256>>>(x, ga);
    gates_kernel<<<BB, 256>>>(ba, n, m, out);
    update_kernel<<<BB * HH / 32, 1024>>>(C, out);
}